// round 6
// baseline (speedup 1.0000x reference)
#include <cuda_runtime.h>
#include <cuda_bf16.h>

#define B_    8192
#define NPAIR 32
#define BN    (B_ * NPAIR)
#define RREL  3
#define KP    136            // padded bf16 row stride (conflict-free for LDS + ldmatrix)

__device__ float g_ui[B_ * 64];
__device__ int   g_cnt[RREL];
__device__ int   g_items[RREL * BN];

__device__ __forceinline__ float lrelu(float x) { return x >= 0.f ? x : 0.01f * x; }

__device__ __forceinline__ void split2(float x0, float x1, unsigned& hi, unsigned& lo) {
    __nv_bfloat16 h0 = __float2bfloat16(x0), h1 = __float2bfloat16(x1);
    float l0 = x0 - __bfloat162float(h0), l1 = x1 - __bfloat162float(h1);
    __nv_bfloat16 e0 = __float2bfloat16(l0), e1 = __float2bfloat16(l1);
    hi = ((unsigned)__bfloat16_as_ushort(h1) << 16) | (unsigned)__bfloat16_as_ushort(h0);
    lo = ((unsigned)__bfloat16_as_ushort(e1) << 16) | (unsigned)__bfloat16_as_ushort(e0);
}

__device__ __forceinline__ unsigned smem_u32(const void* p) {
    unsigned a;
    asm("{ .reg .u64 t; cvta.to.shared.u64 t, %1; cvt.u32.u64 %0, t; }" : "=r"(a) : "l"(p));
    return a;
}

#define MMA(d, a, b) \
    asm volatile("mma.sync.aligned.m16n8k16.row.col.f32.bf16.bf16.f32 " \
        "{%0,%1,%2,%3}, {%4,%5,%6,%7}, {%8,%9}, {%0,%1,%2,%3};" \
        : "+f"((d)[0]), "+f"((d)[1]), "+f"((d)[2]), "+f"((d)[3]) \
        : "r"((a)[0]), "r"((a)[1]), "r"((a)[2]), "r"((a)[3]), "r"((b)[0]), "r"((b)[1]))

#define LDSM4(r0, r1, r2, r3, addr) \
    asm volatile("ldmatrix.sync.aligned.m8n8.x4.shared.b16 {%0,%1,%2,%3}, [%4];" \
        : "=r"(r0), "=r"(r1), "=r"(r2), "=r"(r3) : "r"(addr))

// ---------------- kernel A: ui branch (unchanged, passing) ----------------
__global__ __launch_bounds__(128) void ui_kernel(
    const float* __restrict__ u, const float* __restrict__ iv,
    const float* __restrict__ W0, const float* __restrict__ b0,
    const float* __restrict__ W1, const float* __restrict__ b1)
{
    __shared__ float sx[8][128];
    __shared__ float sh[8][128];
    int tid = threadIdx.x;
    int row0 = blockIdx.x * 8;
    #pragma unroll
    for (int rr = 0; rr < 8; rr++) {
        int row = row0 + rr;
        sx[rr][tid] = (tid < 64) ? u[row * 64 + tid] : iv[row * 64 + tid - 64];
    }
    __syncthreads();
    float acc[8];
    #pragma unroll
    for (int rr = 0; rr < 8; rr++) acc[rr] = 0.f;
    #pragma unroll 4
    for (int k = 0; k < 128; k++) {
        float w = W0[k * 128 + tid];
        #pragma unroll
        for (int rr = 0; rr < 8; rr++) acc[rr] += sx[rr][k] * w;
    }
    float bb = b0[tid];
    #pragma unroll
    for (int rr = 0; rr < 8; rr++) sh[rr][tid] = lrelu(acc[rr] + bb);
    __syncthreads();
    int j = tid & 63, rb = (tid >> 6) * 4;
    float a2[4] = {0.f, 0.f, 0.f, 0.f};
    #pragma unroll 4
    for (int k = 0; k < 128; k++) {
        float w = W1[k * 64 + j];
        #pragma unroll
        for (int q = 0; q < 4; q++) a2[q] += sh[rb + q][k] * w;
    }
    float b2 = b1[j];
    #pragma unroll
    for (int q = 0; q < 4; q++) g_ui[(row0 + rb + q) * 64 + j] = lrelu(a2[q] + b2);
}

// ---------------- zero + bin kernels ----------------
__global__ void zero_cnt_kernel() {
    if (threadIdx.x < RREL) g_cnt[threadIdx.x] = 0;
}

__global__ __launch_bounds__(512) void bin_kernel(const void* __restrict__ s_raw)
{
    __shared__ int bc[RREL], bb[RREL], sis64;
    int tid = threadIdx.x;
    if (tid == 0) {
        const int* p = (const int*)s_raw;
        int any = 0;
        for (int q = 1; q < 257; q += 2) any |= p[q];
        sis64 = (any == 0);
        bc[0] = bc[1] = bc[2] = 0;
    }
    __syncthreads();
    int it = blockIdx.x * 512 + tid;
    const int* s32 = (const int*)s_raw;
    int sv = sis64 ? s32[2 * it] : s32[it];
    sv = min(max(sv, 0), RREL - 1);
    int pos = atomicAdd(&bc[sv], 1);
    __syncthreads();
    if (tid < RREL) bb[tid] = atomicAdd(&g_cnt[tid], bc[tid]);
    __syncthreads();
    g_items[sv * BN + bb[sv] + pos] = it;
}

// ---------------- kernel C: bf16 mma.sync AO branch (ldmatrix fragments) ----------------
#define XH_OFF    0                          // X hi / H hi: 128 x 136 bf16
#define XL_OFF    34816                      // X lo / H lo
#define W0H_OFF   69632                      // W0^T hi: [n=128][k=136]
#define W0L_OFF   104448
#define W1H_OFF   139264                     // W1^T hi: [o=64][h=136]
#define W1L_OFF   156672
#define SB0_OFF   174080                     // float[128]
#define SB1_OFF   174592                     // float[64]
#define SL_OFF    174848                     // int[128]
#define SRED_OFF  175360                     // float[128][4]
#define SMEM_TOT  177408

#define ROWSTEP16 (16 * KP * 2)              // 4352 bytes: 16 rows

__global__ __launch_bounds__(512, 1) void ao_mma_kernel(
    const float* __restrict__ a_emb, const float* __restrict__ o_emb,
    const float* __restrict__ aoW0, const float* __restrict__ aob0,
    const float* __restrict__ aoW1, const float* __restrict__ aob1,
    float* __restrict__ out)
{
    extern __shared__ char smem[];
    unsigned sbase = smem_u32(smem);
    float* sb0  = (float*)(smem + SB0_OFF);
    float* sb1  = (float*)(smem + SB1_OFF);
    int*   sl   = (int*)(smem + SL_OFF);
    float* sred = (float*)(smem + SRED_OFF);

    int tid = threadIdx.x, wid = tid >> 5, lane = tid & 31;
    int gq = lane >> 2, t = lane & 3;

    // ldmatrix per-lane addressing: lanes 0-15 -> 16 rows at k-lo tile,
    // lanes 16-31 -> same 16 rows at k-hi (+8 cols) tile.
    unsigned rowSel = (unsigned)(lane & 15);
    unsigned kSel   = (unsigned)((lane >> 4) << 3);

    int cnt[RREL], nch[RREL];
    #pragma unroll
    for (int r = 0; r < RREL; r++) { cnt[r] = g_cnt[r]; nch[r] = (cnt[r] + 127) >> 7; }
    int tot = nch[0] + nch[1] + nch[2];
    int per = (tot + gridDim.x - 1) / gridDim.x;
    int c_lo = blockIdx.x * per, c_hi = min(tot, c_lo + per);
    int cur_r = -1;

    int mrow = (wid & 3) * 32, ncol = (wid >> 2) * 32;
    int ncol2 = (wid >> 2) * 16;

    // Per-warp ldmatrix base addresses (byte, shared space)
    unsigned aHiB  = sbase + XH_OFF  + ((mrow + rowSel) * KP + kSel) * 2;
    unsigned aLoB  = aHiB + (XL_OFF - XH_OFF);
    unsigned b0HiB = sbase + W0H_OFF + ((ncol + rowSel) * KP + kSel) * 2;
    unsigned b0LoB = b0HiB + (W0L_OFF - W0H_OFF);
    unsigned b1HiB = sbase + W1H_OFF + ((ncol2 + rowSel) * KP + kSel) * 2;
    unsigned b1LoB = b1HiB + (W1L_OFF - W1H_OFF);

    for (int c = c_lo; c < c_hi; c++) {
        int r, ci;
        if (c < nch[0])               { r = 0; ci = c; }
        else if (c < nch[0] + nch[1]) { r = 1; ci = c - nch[0]; }
        else                          { r = 2; ci = c - nch[0] - nch[1]; }
        int base = ci << 7;
        int valid = min(128, cnt[r] - base);

        // ---- weight staging on relation change ----
        if (r != cur_r) {
            cur_r = r;
            const float* w0g = aoW0 + (size_t)r * 16384;   // [k=128][n=128]
            for (int idx = tid; idx < 8192; idx += 512) {
                int n = idx & 127, k = (idx >> 7) * 2;
                unsigned hi, lo;
                split2(w0g[k * 128 + n], w0g[(k + 1) * 128 + n], hi, lo);
                *(unsigned*)(smem + W0H_OFF + (n * KP + k) * 2) = hi;
                *(unsigned*)(smem + W0L_OFF + (n * KP + k) * 2) = lo;
            }
            const float* w1g = aoW1 + (size_t)r * 8192;    // [h=128][o=64]
            for (int idx = tid; idx < 4096; idx += 512) {
                int o = idx & 63, h = (idx >> 6) * 2;
                unsigned hi, lo;
                split2(w1g[h * 64 + o], w1g[(h + 1) * 64 + o], hi, lo);
                *(unsigned*)(smem + W1H_OFF + (o * KP + h) * 2) = hi;
                *(unsigned*)(smem + W1L_OFF + (o * KP + h) * 2) = lo;
            }
            if (tid < 128) sb0[tid] = aob0[r * 128 + tid];
            if (tid < 64)  sb1[tid] = aob1[r * 64 + tid];
        }

        // ---- stage item list + gather X (split hi/lo) ----
        if (tid < 128) sl[tid] = (tid < valid) ? g_items[r * BN + base + tid] : -1;
        __syncthreads();
        {
            int row = tid >> 2, q = tid & 3;
            int g = sl[row];
            int cb = q * 32;
            const float* src = (q < 2) ? a_emb + (size_t)max(g, 0) * 64 + cb
                                       : o_emb + (size_t)max(g, 0) * 64 + (cb - 64);
            #pragma unroll
            for (int i = 0; i < 8; i++) {
                float4 v = (g >= 0) ? *(const float4*)(src + i * 4)
                                    : make_float4(0.f, 0.f, 0.f, 0.f);
                unsigned h0, l0, h1, l1;
                split2(v.x, v.y, h0, l0);
                split2(v.z, v.w, h1, l1);
                int cc = cb + i * 4;
                *(unsigned*)(smem + XH_OFF + (row * KP + cc) * 2)     = h0;
                *(unsigned*)(smem + XH_OFF + (row * KP + cc + 2) * 2) = h1;
                *(unsigned*)(smem + XL_OFF + (row * KP + cc) * 2)     = l0;
                *(unsigned*)(smem + XL_OFF + (row * KP + cc + 2) * 2) = l1;
            }
        }
        __syncthreads();

        // ---- GEMM1: D1[128,128] = X @ W0, 3-term bf16 split ----
        float acc[2][4][4];
        #pragma unroll
        for (int i = 0; i < 2; i++)
            #pragma unroll
            for (int j = 0; j < 4; j++)
                #pragma unroll
                for (int q = 0; q < 4; q++) acc[i][j][q] = 0.f;

        #pragma unroll
        for (int kt = 0; kt < 8; kt++) {
            unsigned ko = (unsigned)kt * 32;
            unsigned ah[2][4], al[2][4], bh[4][2], bl[4][2];
            LDSM4(ah[0][0], ah[0][1], ah[0][2], ah[0][3], aHiB + ko);
            LDSM4(ah[1][0], ah[1][1], ah[1][2], ah[1][3], aHiB + ROWSTEP16 + ko);
            LDSM4(al[0][0], al[0][1], al[0][2], al[0][3], aLoB + ko);
            LDSM4(al[1][0], al[1][1], al[1][2], al[1][3], aLoB + ROWSTEP16 + ko);
            {
                unsigned r0, r1, r2, r3;
                LDSM4(r0, r1, r2, r3, b0HiB + ko);
                bh[0][0] = r0; bh[1][0] = r1; bh[0][1] = r2; bh[1][1] = r3;
                LDSM4(r0, r1, r2, r3, b0HiB + ROWSTEP16 + ko);
                bh[2][0] = r0; bh[3][0] = r1; bh[2][1] = r2; bh[3][1] = r3;
                LDSM4(r0, r1, r2, r3, b0LoB + ko);
                bl[0][0] = r0; bl[1][0] = r1; bl[0][1] = r2; bl[1][1] = r3;
                LDSM4(r0, r1, r2, r3, b0LoB + ROWSTEP16 + ko);
                bl[2][0] = r0; bl[3][0] = r1; bl[2][1] = r2; bl[3][1] = r3;
            }
            #pragma unroll
            for (int ma = 0; ma < 2; ma++)
                #pragma unroll
                for (int na = 0; na < 4; na++) {
                    MMA(acc[ma][na], ah[ma], bh[na]);
                    MMA(acc[ma][na], ah[ma], bl[na]);
                    MMA(acc[ma][na], al[ma], bh[na]);
                }
        }
        __syncthreads();   // all X reads done before overwrite with H

        // ---- epilogue 1: H = lrelu(D1 + b0), split in place of X ----
        #pragma unroll
        for (int ma = 0; ma < 2; ma++) {
            int rr0 = mrow + ma * 16 + gq;
            #pragma unroll
            for (int na = 0; na < 4; na++) {
                int cc = ncol + na * 8 + 2 * t;
                float h0 = lrelu(acc[ma][na][0] + sb0[cc]);
                float h1 = lrelu(acc[ma][na][1] + sb0[cc + 1]);
                float h2 = lrelu(acc[ma][na][2] + sb0[cc]);
                float h3 = lrelu(acc[ma][na][3] + sb0[cc + 1]);
                unsigned hi, lo;
                split2(h0, h1, hi, lo);
                *(unsigned*)(smem + XH_OFF + (rr0 * KP + cc) * 2) = hi;
                *(unsigned*)(smem + XL_OFF + (rr0 * KP + cc) * 2) = lo;
                split2(h2, h3, hi, lo);
                *(unsigned*)(smem + XH_OFF + ((rr0 + 8) * KP + cc) * 2) = hi;
                *(unsigned*)(smem + XL_OFF + ((rr0 + 8) * KP + cc) * 2) = lo;
            }
        }
        __syncthreads();

        // ---- GEMM2: D2[128,64] = H @ W1 ----
        float acc2[2][2][4];
        #pragma unroll
        for (int i = 0; i < 2; i++)
            #pragma unroll
            for (int j = 0; j < 2; j++)
                #pragma unroll
                for (int q = 0; q < 4; q++) acc2[i][j][q] = 0.f;

        #pragma unroll
        for (int kt = 0; kt < 8; kt++) {
            unsigned ko = (unsigned)kt * 32;
            unsigned ah[2][4], al[2][4], bh[2][2], bl[2][2];
            LDSM4(ah[0][0], ah[0][1], ah[0][2], ah[0][3], aHiB + ko);
            LDSM4(ah[1][0], ah[1][1], ah[1][2], ah[1][3], aHiB + ROWSTEP16 + ko);
            LDSM4(al[0][0], al[0][1], al[0][2], al[0][3], aLoB + ko);
            LDSM4(al[1][0], al[1][1], al[1][2], al[1][3], aLoB + ROWSTEP16 + ko);
            {
                unsigned r0, r1, r2, r3;
                LDSM4(r0, r1, r2, r3, b1HiB + ko);
                bh[0][0] = r0; bh[1][0] = r1; bh[0][1] = r2; bh[1][1] = r3;
                LDSM4(r0, r1, r2, r3, b1LoB + ko);
                bl[0][0] = r0; bl[1][0] = r1; bl[0][1] = r2; bl[1][1] = r3;
            }
            #pragma unroll
            for (int ma = 0; ma < 2; ma++)
                #pragma unroll
                for (int na = 0; na < 2; na++) {
                    MMA(acc2[ma][na], ah[ma], bh[na]);
                    MMA(acc2[ma][na], ah[ma], bl[na]);
                    MMA(acc2[ma][na], al[ma], bh[na]);
                }
        }

        // ---- epilogue 2: o = lrelu(D2 + b1); partial dot with ui; reduce ----
        #pragma unroll
        for (int ma = 0; ma < 2; ma++) {
            #pragma unroll
            for (int half = 0; half < 2; half++) {
                int row = mrow + ma * 16 + gq + half * 8;
                int g = sl[row];
                const float* uiP = g_ui + (size_t)(max(g, 0) >> 5) * 64;
                float p = 0.f;
                #pragma unroll
                for (int na = 0; na < 2; na++) {
                    int cc = ncol2 + na * 8 + 2 * t;
                    float2 uv = *(const float2*)(uiP + cc);
                    float o0 = lrelu(acc2[ma][na][half * 2]     + sb1[cc]);
                    float o1 = lrelu(acc2[ma][na][half * 2 + 1] + sb1[cc + 1]);
                    p += o0 * uv.x + o1 * uv.y;
                }
                p += __shfl_xor_sync(0xffffffffu, p, 1);
                p += __shfl_xor_sync(0xffffffffu, p, 2);
                if (t == 0) sred[row * 4 + (wid >> 2)] = p;
            }
        }
        __syncthreads();
        if (tid < 128) {
            int g = sl[tid];
            if (g >= 0)
                out[g] = sred[tid * 4] + sred[tid * 4 + 1] + sred[tid * 4 + 2] + sred[tid * 4 + 3];
        }
        __syncthreads();
    }
}

// ---------------- launch ----------------
extern "C" void kernel_launch(void* const* d_in, const int* in_sizes, int n_in,
                              void* d_out, int out_size)
{
    const float* u    = (const float*)d_in[0];
    const float* iv   = (const float*)d_in[1];
    const float* a    = (const float*)d_in[2];
    const float* o    = (const float*)d_in[3];
    const void*  s    = d_in[4];
    const float* aoW0 = (const float*)d_in[5];
    const float* aob0 = (const float*)d_in[6];
    const float* aoW1 = (const float*)d_in[7];
    const float* aob1 = (const float*)d_in[8];
    const float* uiW0 = (const float*)d_in[9];
    const float* uib0 = (const float*)d_in[10];
    const float* uiW1 = (const float*)d_in[11];
    const float* uib1 = (const float*)d_in[12];
    float* out = (float*)d_out;

    cudaFuncSetAttribute(ao_mma_kernel, cudaFuncAttributeMaxDynamicSharedMemorySize, SMEM_TOT);
    int nsm = 148;
    cudaDeviceGetAttribute(&nsm, cudaDevAttrMultiProcessorCount, 0);

    zero_cnt_kernel<<<1, 32>>>();
    bin_kernel<<<BN / 512, 512>>>(s);
    ui_kernel<<<B_ / 8, 128>>>(u, iv, uiW0, uib0, uiW1, uib1);
    ao_mma_kernel<<<nsm, 512, SMEM_TOT>>>(a, o, aoW0, aob0, aoW1, aob1, out);
}

// round 7
// speedup vs baseline: 1.1144x; 1.1144x over previous
#include <cuda_runtime.h>
#include <cuda_bf16.h>

#define B_    8192
#define NPAIR 32
#define BN    (B_ * NPAIR)
#define RREL  3
#define KP    136            // padded bf16 row stride (conflict-free for ldmatrix)
#define CH    64             // items per chunk (per warp-group)

__device__ float g_ui[B_ * 64];
__device__ int   g_cnt[RREL];
__device__ int   g_items[RREL * BN];

__device__ __forceinline__ float lrelu(float x) { return x >= 0.f ? x : 0.01f * x; }

__device__ __forceinline__ void split2(float x0, float x1, unsigned& hi, unsigned& lo) {
    __nv_bfloat16 h0 = __float2bfloat16(x0), h1 = __float2bfloat16(x1);
    float l0 = x0 - __bfloat162float(h0), l1 = x1 - __bfloat162float(h1);
    __nv_bfloat16 e0 = __float2bfloat16(l0), e1 = __float2bfloat16(l1);
    hi = ((unsigned)__bfloat16_as_ushort(h1) << 16) | (unsigned)__bfloat16_as_ushort(h0);
    lo = ((unsigned)__bfloat16_as_ushort(e1) << 16) | (unsigned)__bfloat16_as_ushort(e0);
}

__device__ __forceinline__ unsigned smem_u32(const void* p) {
    unsigned a;
    asm("{ .reg .u64 t; cvta.to.shared.u64 t, %1; cvt.u32.u64 %0, t; }" : "=r"(a) : "l"(p));
    return a;
}

#define MMA(d, a, b) \
    asm volatile("mma.sync.aligned.m16n8k16.row.col.f32.bf16.bf16.f32 " \
        "{%0,%1,%2,%3}, {%4,%5,%6,%7}, {%8,%9}, {%0,%1,%2,%3};" \
        : "+f"((d)[0]), "+f"((d)[1]), "+f"((d)[2]), "+f"((d)[3]) \
        : "r"((a)[0]), "r"((a)[1]), "r"((a)[2]), "r"((a)[3]), "r"((b)[0]), "r"((b)[1]))

#define LDSM4(r0, r1, r2, r3, addr) \
    asm volatile("ldmatrix.sync.aligned.m8n8.x4.shared.b16 {%0,%1,%2,%3}, [%4];" \
        : "=r"(r0), "=r"(r1), "=r"(r2), "=r"(r3) : "r"(addr))

#define BARG(id) asm volatile("bar.sync %0, 256;" :: "r"(id) : "memory")

// ---------------- kernel A: ui branch (unchanged, passing) ----------------
__global__ __launch_bounds__(128) void ui_kernel(
    const float* __restrict__ u, const float* __restrict__ iv,
    const float* __restrict__ W0, const float* __restrict__ b0,
    const float* __restrict__ W1, const float* __restrict__ b1)
{
    __shared__ float sx[8][128];
    __shared__ float sh[8][128];
    int tid = threadIdx.x;
    int row0 = blockIdx.x * 8;
    #pragma unroll
    for (int rr = 0; rr < 8; rr++) {
        int row = row0 + rr;
        sx[rr][tid] = (tid < 64) ? u[row * 64 + tid] : iv[row * 64 + tid - 64];
    }
    __syncthreads();
    float acc[8];
    #pragma unroll
    for (int rr = 0; rr < 8; rr++) acc[rr] = 0.f;
    #pragma unroll 4
    for (int k = 0; k < 128; k++) {
        float w = W0[k * 128 + tid];
        #pragma unroll
        for (int rr = 0; rr < 8; rr++) acc[rr] += sx[rr][k] * w;
    }
    float bb = b0[tid];
    #pragma unroll
    for (int rr = 0; rr < 8; rr++) sh[rr][tid] = lrelu(acc[rr] + bb);
    __syncthreads();
    int j = tid & 63, rb = (tid >> 6) * 4;
    float a2[4] = {0.f, 0.f, 0.f, 0.f};
    #pragma unroll 4
    for (int k = 0; k < 128; k++) {
        float w = W1[k * 64 + j];
        #pragma unroll
        for (int q = 0; q < 4; q++) a2[q] += sh[rb + q][k] * w;
    }
    float b2 = b1[j];
    #pragma unroll
    for (int q = 0; q < 4; q++) g_ui[(row0 + rb + q) * 64 + j] = lrelu(a2[q] + b2);
}

// ---------------- zero + bin kernels ----------------
__global__ void zero_cnt_kernel() {
    if (threadIdx.x < RREL) g_cnt[threadIdx.x] = 0;
}

__global__ __launch_bounds__(512) void bin_kernel(const void* __restrict__ s_raw)
{
    __shared__ int bc[RREL], bb[RREL], sis64;
    int tid = threadIdx.x;
    if (tid == 0) {
        const int* p = (const int*)s_raw;
        int any = 0;
        for (int q = 1; q < 257; q += 2) any |= p[q];
        sis64 = (any == 0);
        bc[0] = bc[1] = bc[2] = 0;
    }
    __syncthreads();
    int it = blockIdx.x * 512 + tid;
    const int* s32 = (const int*)s_raw;
    int sv = sis64 ? s32[2 * it] : s32[it];
    sv = min(max(sv, 0), RREL - 1);
    int pos = atomicAdd(&bc[sv], 1);
    __syncthreads();
    if (tid < RREL) bb[tid] = atomicAdd(&g_cnt[tid], bc[tid]);
    __syncthreads();
    g_items[sv * BN + bb[sv] + pos] = it;
}

// ---------------- kernel C: bf16 mma.sync AO branch, 2 pipelined warp-groups ----------------
// smem map (bytes):
//   X region  : grp g at g*34816 : XH 64x136 bf16 (17408) then XL (17408)   [69632 total]
//   W0H 69632 (34816), W0L 104448 (34816), W1H 139264 (17408), W1L 156672 (17408)
//   sb0 174080 (512), sb1 174592 (256), sl 174848 (2*64 int = 512), sred 175360 (2*64*4 f = 2048)
#define XBYTES    17408
#define W0H_OFF   69632
#define W0L_OFF   104448
#define W1H_OFF   139264
#define W1L_OFF   156672
#define SB0_OFF   174080
#define SB1_OFF   174592
#define SL_OFF    174848
#define SRED_OFF  175360
#define SMEM_TOT  177408

#define ROWSTEP16 (16 * KP * 2)   // 4352 bytes

__global__ __launch_bounds__(512, 1) void ao_mma_kernel(
    const float* __restrict__ a_emb, const float* __restrict__ o_emb,
    const float* __restrict__ aoW0, const float* __restrict__ aob0,
    const float* __restrict__ aoW1, const float* __restrict__ aob1,
    float* __restrict__ out)
{
    extern __shared__ char smem[];
    unsigned sbase = smem_u32(smem);
    float* sb0 = (float*)(smem + SB0_OFF);
    float* sb1 = (float*)(smem + SB1_OFF);

    int tid = threadIdx.x, wid = tid >> 5, lane = tid & 31;
    int grp = wid >> 3;                 // warp-group 0 / 1
    int wg  = wid & 7;                  // warp id within group
    int tg  = tid & 255;                // thread id within group
    int gq = lane >> 2, t = lane & 3;
    int barid = 1 + grp;

    int*   slg   = (int*)(smem + SL_OFF) + grp * 64;
    float* sredg = (float*)(smem + SRED_OFF) + grp * 256;

    // ldmatrix lane addressing
    unsigned rowSel = (unsigned)(lane & 15);
    unsigned kSel   = (unsigned)((lane >> 4) << 3);

    // warp tile layout within group: GEMM1 32x32, GEMM2 32x16
    int mrow  = (wg & 1) * 32;
    int ncol  = (wg >> 1) * 32;
    int ncol2 = (wg >> 1) * 16;

    unsigned xbase = sbase + (unsigned)grp * (2 * XBYTES);
    unsigned aHiB  = xbase + ((mrow + rowSel) * KP + kSel) * 2;
    unsigned aLoB  = aHiB + XBYTES;
    unsigned b0HiB = sbase + W0H_OFF + ((ncol + rowSel) * KP + kSel) * 2;
    unsigned b0LoB = b0HiB + (W0L_OFF - W0H_OFF);
    unsigned b1HiB = sbase + W1H_OFF + ((ncol2 + rowSel) * KP + kSel) * 2;
    unsigned b1LoB = b1HiB + (W1L_OFF - W1H_OFF);

    int cnt[RREL], rs[RREL + 1];
    rs[0] = 0;
    #pragma unroll
    for (int r = 0; r < RREL; r++) {
        cnt[r] = g_cnt[r];
        rs[r + 1] = rs[r] + ((cnt[r] + CH - 1) / CH);
    }
    int tot = rs[RREL];
    int per = (tot + gridDim.x - 1) / gridDim.x;
    int c_lo = blockIdx.x * per, c_hi = min(tot, c_lo + per);

    for (int r = 0; r < RREL; r++) {
        int lo = max(c_lo, rs[r]), hi = min(c_hi, rs[r + 1]);
        if (lo >= hi) continue;

        // ---- cooperative weight staging (whole CTA) ----
        {
            const float* w0g = aoW0 + (size_t)r * 16384;   // [k=128][n=128]
            for (int idx = tid; idx < 8192; idx += 512) {
                int n = idx & 127, k = (idx >> 7) * 2;
                unsigned hi_, lo_;
                split2(w0g[k * 128 + n], w0g[(k + 1) * 128 + n], hi_, lo_);
                *(unsigned*)(smem + W0H_OFF + (n * KP + k) * 2) = hi_;
                *(unsigned*)(smem + W0L_OFF + (n * KP + k) * 2) = lo_;
            }
            const float* w1g = aoW1 + (size_t)r * 8192;    // [h=128][o=64]
            for (int idx = tid; idx < 4096; idx += 512) {
                int o = idx & 63, h = (idx >> 6) * 2;
                unsigned hi_, lo_;
                split2(w1g[h * 64 + o], w1g[(h + 1) * 64 + o], hi_, lo_);
                *(unsigned*)(smem + W1H_OFF + (o * KP + h) * 2) = hi_;
                *(unsigned*)(smem + W1L_OFF + (o * KP + h) * 2) = lo_;
            }
            if (tid < 128) sb0[tid] = aob0[r * 128 + tid];
            if (tid < 64)  sb1[tid] = aob1[r * 64 + tid];
        }
        __syncthreads();

        // ---- group-interleaved chunk loop ----
        for (int c = lo + grp; c < hi; c += 2) {
            int ci = c - rs[r];
            int base = ci * CH;
            int valid = min(CH, cnt[r] - base);

            // stage item list
            if (tg < 64) slg[tg] = (tg < valid) ? g_items[r * BN + base + tg] : -1;
            BARG(barid);

            // gather X (64 rows, 256 threads: 4 threads/row)
            {
                int row = tg >> 2, q = tg & 3;
                int g = slg[row];
                int cb = q * 32;
                const float* src = (q < 2) ? a_emb + (size_t)max(g, 0) * 64 + cb
                                           : o_emb + (size_t)max(g, 0) * 64 + (cb - 64);
                #pragma unroll
                for (int i = 0; i < 8; i++) {
                    float4 v = (g >= 0) ? *(const float4*)(src + i * 4)
                                        : make_float4(0.f, 0.f, 0.f, 0.f);
                    unsigned h0, l0, h1, l1;
                    split2(v.x, v.y, h0, l0);
                    split2(v.z, v.w, h1, l1);
                    int cc = cb + i * 4;
                    unsigned d = xbase + (row * KP + cc) * 2 - sbase;
                    *(unsigned*)(smem + d)              = h0;
                    *(unsigned*)(smem + d + 4)          = h1;
                    *(unsigned*)(smem + d + XBYTES)     = l0;
                    *(unsigned*)(smem + d + XBYTES + 4) = l1;
                }
            }
            BARG(barid);

            // ---- GEMM1: D1[64,128] = X @ W0 (3-term split) ----
            float acc[2][4][4];
            #pragma unroll
            for (int i = 0; i < 2; i++)
                #pragma unroll
                for (int j = 0; j < 4; j++)
                    #pragma unroll
                    for (int q = 0; q < 4; q++) acc[i][j][q] = 0.f;

            #pragma unroll
            for (int kt = 0; kt < 8; kt++) {
                unsigned ko = (unsigned)kt * 32;
                unsigned ah[2][4], al[2][4], bh[4][2], bl[4][2];
                LDSM4(ah[0][0], ah[0][1], ah[0][2], ah[0][3], aHiB + ko);
                LDSM4(ah[1][0], ah[1][1], ah[1][2], ah[1][3], aHiB + ROWSTEP16 + ko);
                LDSM4(al[0][0], al[0][1], al[0][2], al[0][3], aLoB + ko);
                LDSM4(al[1][0], al[1][1], al[1][2], al[1][3], aLoB + ROWSTEP16 + ko);
                {
                    unsigned r0, r1, r2, r3;
                    LDSM4(r0, r1, r2, r3, b0HiB + ko);
                    bh[0][0] = r0; bh[1][0] = r1; bh[0][1] = r2; bh[1][1] = r3;
                    LDSM4(r0, r1, r2, r3, b0HiB + ROWSTEP16 + ko);
                    bh[2][0] = r0; bh[3][0] = r1; bh[2][1] = r2; bh[3][1] = r3;
                    LDSM4(r0, r1, r2, r3, b0LoB + ko);
                    bl[0][0] = r0; bl[1][0] = r1; bl[0][1] = r2; bl[1][1] = r3;
                    LDSM4(r0, r1, r2, r3, b0LoB + ROWSTEP16 + ko);
                    bl[2][0] = r0; bl[3][0] = r1; bl[2][1] = r2; bl[3][1] = r3;
                }
                #pragma unroll
                for (int ma = 0; ma < 2; ma++)
                    #pragma unroll
                    for (int na = 0; na < 4; na++) {
                        MMA(acc[ma][na], ah[ma], bh[na]);
                        MMA(acc[ma][na], ah[ma], bl[na]);
                        MMA(acc[ma][na], al[ma], bh[na]);
                    }
            }
            BARG(barid);   // all X reads done before overwrite with H

            // ---- epilogue 1: H = lrelu(D1 + b0), split in place of X ----
            #pragma unroll
            for (int ma = 0; ma < 2; ma++) {
                int rr0 = mrow + ma * 16 + gq;
                #pragma unroll
                for (int na = 0; na < 4; na++) {
                    int cc = ncol + na * 8 + 2 * t;
                    float h0 = lrelu(acc[ma][na][0] + sb0[cc]);
                    float h1 = lrelu(acc[ma][na][1] + sb0[cc + 1]);
                    float h2 = lrelu(acc[ma][na][2] + sb0[cc]);
                    float h3 = lrelu(acc[ma][na][3] + sb0[cc + 1]);
                    unsigned hi_, lo_;
                    unsigned d = xbase + (rr0 * KP + cc) * 2 - sbase;
                    split2(h0, h1, hi_, lo_);
                    *(unsigned*)(smem + d)          = hi_;
                    *(unsigned*)(smem + d + XBYTES) = lo_;
                    split2(h2, h3, hi_, lo_);
                    unsigned d2 = d + 8 * KP * 2;
                    *(unsigned*)(smem + d2)          = hi_;
                    *(unsigned*)(smem + d2 + XBYTES) = lo_;
                }
            }
            BARG(barid);

            // ---- GEMM2: D2[64,64] = H @ W1 ----
            float acc2[2][2][4];
            #pragma unroll
            for (int i = 0; i < 2; i++)
                #pragma unroll
                for (int j = 0; j < 2; j++)
                    #pragma unroll
                    for (int q = 0; q < 4; q++) acc2[i][j][q] = 0.f;

            #pragma unroll
            for (int kt = 0; kt < 8; kt++) {
                unsigned ko = (unsigned)kt * 32;
                unsigned ah[2][4], al[2][4], bh[2][2], bl[2][2];
                LDSM4(ah[0][0], ah[0][1], ah[0][2], ah[0][3], aHiB + ko);
                LDSM4(ah[1][0], ah[1][1], ah[1][2], ah[1][3], aHiB + ROWSTEP16 + ko);
                LDSM4(al[0][0], al[0][1], al[0][2], al[0][3], aLoB + ko);
                LDSM4(al[1][0], al[1][1], al[1][2], al[1][3], aLoB + ROWSTEP16 + ko);
                {
                    unsigned r0, r1, r2, r3;
                    LDSM4(r0, r1, r2, r3, b1HiB + ko);
                    bh[0][0] = r0; bh[1][0] = r1; bh[0][1] = r2; bh[1][1] = r3;
                    LDSM4(r0, r1, r2, r3, b1LoB + ko);
                    bl[0][0] = r0; bl[1][0] = r1; bl[0][1] = r2; bl[1][1] = r3;
                }
                #pragma unroll
                for (int ma = 0; ma < 2; ma++)
                    #pragma unroll
                    for (int na = 0; na < 2; na++) {
                        MMA(acc2[ma][na], ah[ma], bh[na]);
                        MMA(acc2[ma][na], ah[ma], bl[na]);
                        MMA(acc2[ma][na], al[ma], bh[na]);
                    }
            }

            // ---- epilogue 2: o = lrelu(D2 + b1); partial dot with ui; reduce ----
            #pragma unroll
            for (int ma = 0; ma < 2; ma++) {
                #pragma unroll
                for (int half = 0; half < 2; half++) {
                    int row = mrow + ma * 16 + gq + half * 8;
                    int g = slg[row];
                    const float* uiP = g_ui + (size_t)(max(g, 0) >> 5) * 64;
                    float p = 0.f;
                    #pragma unroll
                    for (int na = 0; na < 2; na++) {
                        int cc = ncol2 + na * 8 + 2 * t;
                        float2 uv = *(const float2*)(uiP + cc);
                        float o0 = lrelu(acc2[ma][na][half * 2]     + sb1[cc]);
                        float o1 = lrelu(acc2[ma][na][half * 2 + 1] + sb1[cc + 1]);
                        p += o0 * uv.x + o1 * uv.y;
                    }
                    p += __shfl_xor_sync(0xffffffffu, p, 1);
                    p += __shfl_xor_sync(0xffffffffu, p, 2);
                    if (t == 0) sredg[row * 4 + (wg >> 1)] = p;
                }
            }
            BARG(barid);
            if (tg < 64) {
                int g = slg[tg];
                if (g >= 0)
                    out[g] = sredg[tg * 4] + sredg[tg * 4 + 1]
                           + sredg[tg * 4 + 2] + sredg[tg * 4 + 3];
            }
            BARG(barid);
        }
        __syncthreads();   // both groups done before next relation's weight reload
    }
}

// ---------------- launch ----------------
extern "C" void kernel_launch(void* const* d_in, const int* in_sizes, int n_in,
                              void* d_out, int out_size)
{
    const float* u    = (const float*)d_in[0];
    const float* iv   = (const float*)d_in[1];
    const float* a    = (const float*)d_in[2];
    const float* o    = (const float*)d_in[3];
    const void*  s    = d_in[4];
    const float* aoW0 = (const float*)d_in[5];
    const float* aob0 = (const float*)d_in[6];
    const float* aoW1 = (const float*)d_in[7];
    const float* aob1 = (const float*)d_in[8];
    const float* uiW0 = (const float*)d_in[9];
    const float* uib0 = (const float*)d_in[10];
    const float* uiW1 = (const float*)d_in[11];
    const float* uib1 = (const float*)d_in[12];
    float* out = (float*)d_out;

    cudaFuncSetAttribute(ao_mma_kernel, cudaFuncAttributeMaxDynamicSharedMemorySize, SMEM_TOT);
    int nsm = 148;
    cudaDeviceGetAttribute(&nsm, cudaDevAttrMultiProcessorCount, 0);

    zero_cnt_kernel<<<1, 32>>>();
    bin_kernel<<<BN / 512, 512>>>(s);
    ui_kernel<<<B_ / 8, 128>>>(u, iv, uiW0, uib0, uiW1, uib1);
    ao_mma_kernel<<<nsm, 512, SMEM_TOT>>>(a, o, aoW0, aob0, aoW1, aob1, out);
}

// round 10
// speedup vs baseline: 1.1349x; 1.0184x over previous
#include <cuda_runtime.h>
#include <cuda_bf16.h>

#define B_    8192
#define NPAIR 32
#define BN    (B_ * NPAIR)
#define RREL  3
#define KP    136            // padded bf16 row stride (conflict-free for ldmatrix)
#define CH    64             // items per chunk (per warp-group)

__device__ float g_ui[B_ * 64];
__device__ int   g_cnt[RREL];
__device__ int   g_items[RREL * BN];

__device__ __forceinline__ float lrelu(float x) { return x >= 0.f ? x : 0.01f * x; }

__device__ __forceinline__ void split2(float x0, float x1, unsigned& hi, unsigned& lo) {
    __nv_bfloat16 h0 = __float2bfloat16(x0), h1 = __float2bfloat16(x1);
    float l0 = x0 - __bfloat162float(h0), l1 = x1 - __bfloat162float(h1);
    __nv_bfloat16 e0 = __float2bfloat16(l0), e1 = __float2bfloat16(l1);
    hi = ((unsigned)__bfloat16_as_ushort(h1) << 16) | (unsigned)__bfloat16_as_ushort(h0);
    lo = ((unsigned)__bfloat16_as_ushort(e1) << 16) | (unsigned)__bfloat16_as_ushort(e0);
}

__device__ __forceinline__ unsigned smem_u32(const void* p) {
    unsigned a;
    asm("{ .reg .u64 t; cvta.to.shared.u64 t, %1; cvt.u32.u64 %0, t; }" : "=r"(a) : "l"(p));
    return a;
}

#define MMA(d, a, b) \
    asm volatile("mma.sync.aligned.m16n8k16.row.col.f32.bf16.bf16.f32 " \
        "{%0,%1,%2,%3}, {%4,%5,%6,%7}, {%8,%9}, {%0,%1,%2,%3};" \
        : "+f"((d)[0]), "+f"((d)[1]), "+f"((d)[2]), "+f"((d)[3]) \
        : "r"((a)[0]), "r"((a)[1]), "r"((a)[2]), "r"((a)[3]), "r"((b)[0]), "r"((b)[1]))

#define LDSM4(r0, r1, r2, r3, addr) \
    asm volatile("ldmatrix.sync.aligned.m8n8.x4.shared.b16 {%0,%1,%2,%3}, [%4];" \
        : "=r"(r0), "=r"(r1), "=r"(r2), "=r"(r3) : "r"(addr))

#define BARG(id) asm volatile("bar.sync %0, 256;" :: "r"(id) : "memory")

// ---------------- kernel A: ui branch (unchanged, passing) ----------------
__global__ __launch_bounds__(128) void ui_kernel(
    const float* __restrict__ u, const float* __restrict__ iv,
    const float* __restrict__ W0, const float* __restrict__ b0,
    const float* __restrict__ W1, const float* __restrict__ b1)
{
    __shared__ float sx[8][128];
    __shared__ float sh[8][128];
    int tid = threadIdx.x;
    int row0 = blockIdx.x * 8;
    #pragma unroll
    for (int rr = 0; rr < 8; rr++) {
        int row = row0 + rr;
        sx[rr][tid] = (tid < 64) ? u[row * 64 + tid] : iv[row * 64 + tid - 64];
    }
    __syncthreads();
    float acc[8];
    #pragma unroll
    for (int rr = 0; rr < 8; rr++) acc[rr] = 0.f;
    #pragma unroll 4
    for (int k = 0; k < 128; k++) {
        float w = W0[k * 128 + tid];
        #pragma unroll
        for (int rr = 0; rr < 8; rr++) acc[rr] += sx[rr][k] * w;
    }
    float bb = b0[tid];
    #pragma unroll
    for (int rr = 0; rr < 8; rr++) sh[rr][tid] = lrelu(acc[rr] + bb);
    __syncthreads();
    int j = tid & 63, rb = (tid >> 6) * 4;
    float a2[4] = {0.f, 0.f, 0.f, 0.f};
    #pragma unroll 4
    for (int k = 0; k < 128; k++) {
        float w = W1[k * 64 + j];
        #pragma unroll
        for (int q = 0; q < 4; q++) a2[q] += sh[rb + q][k] * w;
    }
    float b2 = b1[j];
    #pragma unroll
    for (int q = 0; q < 4; q++) g_ui[(row0 + rb + q) * 64 + j] = lrelu(a2[q] + b2);
}

// ---------------- zero + bin kernels ----------------
__global__ void zero_cnt_kernel() {
    if (threadIdx.x < RREL) g_cnt[threadIdx.x] = 0;
}

__global__ __launch_bounds__(512) void bin_kernel(const void* __restrict__ s_raw)
{
    __shared__ int bc[RREL], bb[RREL], sis64;
    int tid = threadIdx.x;
    if (tid == 0) {
        const int* p = (const int*)s_raw;
        int any = 0;
        for (int q = 1; q < 257; q += 2) any |= p[q];
        sis64 = (any == 0);
        bc[0] = bc[1] = bc[2] = 0;
    }
    __syncthreads();
    int it = blockIdx.x * 512 + tid;
    const int* s32 = (const int*)s_raw;
    int sv = sis64 ? s32[2 * it] : s32[it];
    sv = min(max(sv, 0), RREL - 1);
    int pos = atomicAdd(&bc[sv], 1);
    __syncthreads();
    if (tid < RREL) bb[tid] = atomicAdd(&g_cnt[tid], bc[tid]);
    __syncthreads();
    g_items[sv * BN + bb[sv] + pos] = it;
}

// ---------------- kernel C: bf16 mma.sync AO branch, 2 pipelined warp-groups ----------------
#define XBYTES    17408
#define W0H_OFF   69632
#define W0L_OFF   104448
#define W1H_OFF   139264
#define W1L_OFF   156672
#define SB0_OFF   174080
#define SB1_OFF   174592
#define SL_OFF    174848
#define SRED_OFF  175360
#define SMEM_TOT  177408

#define ROWSTEP16 (16 * KP * 2)   // 4352 bytes

__global__ __launch_bounds__(512, 1) void ao_mma_kernel(
    const float* __restrict__ a_emb, const float* __restrict__ o_emb,
    const float* __restrict__ aoW0, const float* __restrict__ aob0,
    const float* __restrict__ aoW1, const float* __restrict__ aob1,
    float* __restrict__ out)
{
    extern __shared__ char smem[];
    unsigned sbase = smem_u32(smem);
    float* sb0 = (float*)(smem + SB0_OFF);
    float* sb1 = (float*)(smem + SB1_OFF);

    int tid = threadIdx.x, wid = tid >> 5, lane = tid & 31;
    int grp = wid >> 3;
    int wg  = wid & 7;
    int tg  = tid & 255;
    int gq = lane >> 2, t = lane & 3;
    int barid = 1 + grp;

    int*   slg   = (int*)(smem + SL_OFF) + grp * 64;
    float* sredg = (float*)(smem + SRED_OFF) + grp * 256;

    unsigned rowSel = (unsigned)(lane & 15);
    unsigned kSel   = (unsigned)((lane >> 4) << 3);

    int mrow  = (wg & 1) * 32;
    int ncol  = (wg >> 1) * 32;
    int ncol2 = (wg >> 1) * 16;

    unsigned xbase = sbase + (unsigned)grp * (2 * XBYTES);
    unsigned aHiB  = xbase + ((mrow + rowSel) * KP + kSel) * 2;
    unsigned aLoB  = aHiB + XBYTES;
    unsigned b0HiB = sbase + W0H_OFF + ((ncol + rowSel) * KP + kSel) * 2;
    unsigned b0LoB = b0HiB + (W0L_OFF - W0H_OFF);
    unsigned b1HiB = sbase + W1H_OFF + ((ncol2 + rowSel) * KP + kSel) * 2;
    unsigned b1LoB = b1HiB + (W1L_OFF - W1H_OFF);

    int cnt[RREL], rs[RREL + 1];
    rs[0] = 0;
    #pragma unroll
    for (int r = 0; r < RREL; r++) {
        cnt[r] = g_cnt[r];
        rs[r + 1] = rs[r] + ((cnt[r] + CH - 1) / CH);
    }
    int tot = rs[RREL];
    int per = (tot + gridDim.x - 1) / gridDim.x;
    int c_lo = blockIdx.x * per, c_hi = min(tot, c_lo + per);

    for (int r = 0; r < RREL; r++) {
        int lo = max(c_lo, rs[r]), hi = min(c_hi, rs[r + 1]);
        if (lo >= hi) continue;

        // ---- cooperative weight staging (whole CTA) ----
        {
            const float* w0g = aoW0 + (size_t)r * 16384;
            for (int idx = tid; idx < 8192; idx += 512) {
                int n = idx & 127, k = (idx >> 7) * 2;
                unsigned hi_, lo_;
                split2(w0g[k * 128 + n], w0g[(k + 1) * 128 + n], hi_, lo_);
                *(unsigned*)(smem + W0H_OFF + (n * KP + k) * 2) = hi_;
                *(unsigned*)(smem + W0L_OFF + (n * KP + k) * 2) = lo_;
            }
            const float* w1g = aoW1 + (size_t)r * 8192;
            for (int idx = tid; idx < 4096; idx += 512) {
                int o = idx & 63, h = (idx >> 6) * 2;
                unsigned hi_, lo_;
                split2(w1g[h * 64 + o], w1g[(h + 1) * 64 + o], hi_, lo_);
                *(unsigned*)(smem + W1H_OFF + (o * KP + h) * 2) = hi_;
                *(unsigned*)(smem + W1L_OFF + (o * KP + h) * 2) = lo_;
            }
            if (tid < 128) sb0[tid] = aob0[r * 128 + tid];
            if (tid < 64)  sb1[tid] = aob1[r * 64 + tid];
        }
        __syncthreads();

        // ---- group-interleaved chunk loop ----
        for (int c = lo + grp; c < hi; c += 2) {
            int ci = c - rs[r];
            int base = ci * CH;
            int valid = min(CH, cnt[r] - base);

            if (tg < 64) slg[tg] = (tg < valid) ? g_items[r * BN + base + tg] : -1;
            BARG(barid);

            // gather X (64 rows, 256 threads: 4 threads/row)
            {
                int row = tg >> 2, q = tg & 3;
                int g = slg[row];
                int cb = q * 32;
                const float* src = (q < 2) ? a_emb + (size_t)max(g, 0) * 64 + cb
                                           : o_emb + (size_t)max(g, 0) * 64 + (cb - 64);
                #pragma unroll
                for (int i = 0; i < 8; i++) {
                    float4 v = (g >= 0) ? *(const float4*)(src + i * 4)
                                        : make_float4(0.f, 0.f, 0.f, 0.f);
                    unsigned h0, l0, h1, l1;
                    split2(v.x, v.y, h0, l0);
                    split2(v.z, v.w, h1, l1);
                    int cc = cb + i * 4;
                    unsigned d = xbase + (row * KP + cc) * 2 - sbase;
                    *(unsigned*)(smem + d)              = h0;
                    *(unsigned*)(smem + d + 4)          = h1;
                    *(unsigned*)(smem + d + XBYTES)     = l0;
                    *(unsigned*)(smem + d + XBYTES + 4) = l1;
                }
            }
            BARG(barid);

            // ---- GEMM1: D1[64,128] = X @ W0 (3-term split, term-major issue) ----
            float acc[2][4][4];
            #pragma unroll
            for (int i = 0; i < 2; i++)
                #pragma unroll
                for (int j = 0; j < 4; j++)
                    #pragma unroll
                    for (int q = 0; q < 4; q++) acc[i][j][q] = 0.f;

            #pragma unroll
            for (int kt = 0; kt < 8; kt++) {
                unsigned ko = (unsigned)kt * 32;
                unsigned ah[2][4], al[2][4], bh[4][2], bl[4][2];
                LDSM4(ah[0][0], ah[0][1], ah[0][2], ah[0][3], aHiB + ko);
                LDSM4(ah[1][0], ah[1][1], ah[1][2], ah[1][3], aHiB + ROWSTEP16 + ko);
                LDSM4(al[0][0], al[0][1], al[0][2], al[0][3], aLoB + ko);
                LDSM4(al[1][0], al[1][1], al[1][2], al[1][3], aLoB + ROWSTEP16 + ko);
                {
                    unsigned r0, r1, r2, r3;
                    LDSM4(r0, r1, r2, r3, b0HiB + ko);
                    bh[0][0] = r0; bh[1][0] = r1; bh[0][1] = r2; bh[1][1] = r3;
                    LDSM4(r0, r1, r2, r3, b0HiB + ROWSTEP16 + ko);
                    bh[2][0] = r0; bh[3][0] = r1; bh[2][1] = r2; bh[3][1] = r3;
                    LDSM4(r0, r1, r2, r3, b0LoB + ko);
                    bl[0][0] = r0; bl[1][0] = r1; bl[0][1] = r2; bl[1][1] = r3;
                    LDSM4(r0, r1, r2, r3, b0LoB + ROWSTEP16 + ko);
                    bl[2][0] = r0; bl[3][0] = r1; bl[2][1] = r2; bl[3][1] = r3;
                }
                // term-major: 8 independent accumulators between dependent reuses
                #pragma unroll
                for (int na = 0; na < 4; na++) {
                    MMA(acc[0][na], ah[0], bh[na]);
                    MMA(acc[1][na], ah[1], bh[na]);
                }
                #pragma unroll
                for (int na = 0; na < 4; na++) {
                    MMA(acc[0][na], ah[0], bl[na]);
                    MMA(acc[1][na], ah[1], bl[na]);
                }
                #pragma unroll
                for (int na = 0; na < 4; na++) {
                    MMA(acc[0][na], al[0], bh[na]);
                    MMA(acc[1][na], al[1], bh[na]);
                }
            }
            BARG(barid);   // all X reads done before overwrite with H

            // ---- epilogue 1: H = lrelu(D1 + b0), split in place of X ----
            #pragma unroll
            for (int ma = 0; ma < 2; ma++) {
                int rr0 = mrow + ma * 16 + gq;
                #pragma unroll
                for (int na = 0; na < 4; na++) {
                    int cc = ncol + na * 8 + 2 * t;
                    float h0 = lrelu(acc[ma][na][0] + sb0[cc]);
                    float h1 = lrelu(acc[ma][na][1] + sb0[cc + 1]);
                    float h2 = lrelu(acc[ma][na][2] + sb0[cc]);
                    float h3 = lrelu(acc[ma][na][3] + sb0[cc + 1]);
                    unsigned hi_, lo_;
                    unsigned d = xbase + (rr0 * KP + cc) * 2 - sbase;
                    split2(h0, h1, hi_, lo_);
                    *(unsigned*)(smem + d)          = hi_;
                    *(unsigned*)(smem + d + XBYTES) = lo_;
                    split2(h2, h3, hi_, lo_);
                    unsigned d2 = d + 8 * KP * 2;
                    *(unsigned*)(smem + d2)          = hi_;
                    *(unsigned*)(smem + d2 + XBYTES) = lo_;
                }
            }
            BARG(barid);

            // ---- GEMM2: D2[64,64] = H @ W1 (term-major issue) ----
            float acc2[2][2][4];
            #pragma unroll
            for (int i = 0; i < 2; i++)
                #pragma unroll
                for (int j = 0; j < 2; j++)
                    #pragma unroll
                    for (int q = 0; q < 4; q++) acc2[i][j][q] = 0.f;

            #pragma unroll
            for (int kt = 0; kt < 8; kt++) {
                unsigned ko = (unsigned)kt * 32;
                unsigned ah[2][4], al[2][4], bh[2][2], bl[2][2];
                LDSM4(ah[0][0], ah[0][1], ah[0][2], ah[0][3], aHiB + ko);
                LDSM4(ah[1][0], ah[1][1], ah[1][2], ah[1][3], aHiB + ROWSTEP16 + ko);
                LDSM4(al[0][0], al[0][1], al[0][2], al[0][3], aLoB + ko);
                LDSM4(al[1][0], al[1][1], al[1][2], al[1][3], aLoB + ROWSTEP16 + ko);
                {
                    unsigned r0, r1, r2, r3;
                    LDSM4(r0, r1, r2, r3, b1HiB + ko);
                    bh[0][0] = r0; bh[1][0] = r1; bh[0][1] = r2; bh[1][1] = r3;
                    LDSM4(r0, r1, r2, r3, b1LoB + ko);
                    bl[0][0] = r0; bl[1][0] = r1; bl[0][1] = r2; bl[1][1] = r3;
                }
                #pragma unroll
                for (int na = 0; na < 2; na++) {
                    MMA(acc2[0][na], ah[0], bh[na]);
                    MMA(acc2[1][na], ah[1], bh[na]);
                }
                #pragma unroll
                for (int na = 0; na < 2; na++) {
                    MMA(acc2[0][na], ah[0], bl[na]);
                    MMA(acc2[1][na], ah[1], bl[na]);
                }
                #pragma unroll
                for (int na = 0; na < 2; na++) {
                    MMA(acc2[0][na], al[0], bh[na]);
                    MMA(acc2[1][na], al[1], bh[na]);
                }
            }

            // ---- epilogue 2: o = lrelu(D2 + b1); partial dot with ui; reduce ----
            #pragma unroll
            for (int ma = 0; ma < 2; ma++) {
                #pragma unroll
                for (int half = 0; half < 2; half++) {
                    int row = mrow + ma * 16 + gq + half * 8;
                    int g = slg[row];
                    const float* uiP = g_ui + (size_t)(max(g, 0) >> 5) * 64;
                    float p = 0.f;
                    #pragma unroll
                    for (int na = 0; na < 2; na++) {
                        int cc = ncol2 + na * 8 + 2 * t;
                        float2 uv = *(const float2*)(uiP + cc);
                        float o0 = lrelu(acc2[ma][na][half * 2]     + sb1[cc]);
                        float o1 = lrelu(acc2[ma][na][half * 2 + 1] + sb1[cc + 1]);
                        p += o0 * uv.x + o1 * uv.y;
                    }
                    p += __shfl_xor_sync(0xffffffffu, p, 1);
                    p += __shfl_xor_sync(0xffffffffu, p, 2);
                    if (t == 0) sredg[row * 4 + (wg >> 1)] = p;
                }
            }
            BARG(barid);
            if (tg < 64) {
                int g = slg[tg];
                if (g >= 0)
                    out[g] = sredg[tg * 4] + sredg[tg * 4 + 1]
                           + sredg[tg * 4 + 2] + sredg[tg * 4 + 3];
            }
            BARG(barid);
        }
        __syncthreads();
    }
}

// ---------------- launch ----------------
extern "C" void kernel_launch(void* const* d_in, const int* in_sizes, int n_in,
                              void* d_out, int out_size)
{
    const float* u    = (const float*)d_in[0];
    const float* iv   = (const float*)d_in[1];
    const float* a    = (const float*)d_in[2];
    const float* o    = (const float*)d_in[3];
    const void*  s    = d_in[4];
    const float* aoW0 = (const float*)d_in[5];
    const float* aob0 = (const float*)d_in[6];
    const float* aoW1 = (const float*)d_in[7];
    const float* aob1 = (const float*)d_in[8];
    const float* uiW0 = (const float*)d_in[9];
    const float* uib0 = (const float*)d_in[10];
    const float* uiW1 = (const float*)d_in[11];
    const float* uib1 = (const float*)d_in[12];
    float* out = (float*)d_out;

    cudaFuncSetAttribute(ao_mma_kernel, cudaFuncAttributeMaxDynamicSharedMemorySize, SMEM_TOT);
    int nsm = 148;
    cudaDeviceGetAttribute(&nsm, cudaDevAttrMultiProcessorCount, 0);

    zero_cnt_kernel<<<1, 32>>>();
    bin_kernel<<<BN / 512, 512>>>(s);
    ui_kernel<<<B_ / 8, 128>>>(u, iv, uiW0, uib0, uiW1, uib1);
    ao_mma_kernel<<<nsm, 512, SMEM_TOT>>>(a, o, aoW0, aob0, aoW1, aob1, out);
}

// round 11
// speedup vs baseline: 1.1455x; 1.0093x over previous
#include <cuda_runtime.h>
#include <cuda_bf16.h>

#define B_    8192
#define NPAIR 32
#define BN    (B_ * NPAIR)
#define RREL  3
#define KP    136            // padded bf16 row stride (conflict-free for ldmatrix)
#define CH    64             // items per chunk (per warp-group)

__device__ float g_ui[B_ * 64];
__device__ int   g_cnt[RREL];
__device__ int   g_items[RREL * BN];

__device__ __forceinline__ float lrelu(float x) { return x >= 0.f ? x : 0.01f * x; }

// Truncation-based 2-way bf16 split: hi = bit-truncated bf16 (exact residual),
// lo = rn(x - hi). Pair error <= 2^-17 |x|.
__device__ __forceinline__ void split2(float x0, float x1, unsigned& hi, unsigned& lo) {
    unsigned u0 = __float_as_uint(x0), u1 = __float_as_uint(x1);
    hi = __byte_perm(u0, u1, 0x7632);            // {u1[31:16], u0[31:16]}
    float l0 = x0 - __uint_as_float(u0 & 0xFFFF0000u);
    float l1 = x1 - __uint_as_float(u1 & 0xFFFF0000u);
    asm("cvt.rn.bf16x2.f32 %0, %1, %2;" : "=r"(lo) : "f"(l1), "f"(l0));
}

__device__ __forceinline__ unsigned smem_u32(const void* p) {
    unsigned a;
    asm("{ .reg .u64 t; cvta.to.shared.u64 t, %1; cvt.u32.u64 %0, t; }" : "=r"(a) : "l"(p));
    return a;
}

#define MMA(d, a, b) \
    asm volatile("mma.sync.aligned.m16n8k16.row.col.f32.bf16.bf16.f32 " \
        "{%0,%1,%2,%3}, {%4,%5,%6,%7}, {%8,%9}, {%0,%1,%2,%3};" \
        : "+f"((d)[0]), "+f"((d)[1]), "+f"((d)[2]), "+f"((d)[3]) \
        : "r"((a)[0]), "r"((a)[1]), "r"((a)[2]), "r"((a)[3]), "r"((b)[0]), "r"((b)[1]))

#define LDSM4(r0, r1, r2, r3, addr) \
    asm volatile("ldmatrix.sync.aligned.m8n8.x4.shared.b16 {%0,%1,%2,%3}, [%4];" \
        : "=r"(r0), "=r"(r1), "=r"(r2), "=r"(r3) : "r"(addr))

#define BARG(id) asm volatile("bar.sync %0, 256;" :: "r"(id) : "memory")

// ---------------- kernel A: ui branch (unchanged, passing) ----------------
__global__ __launch_bounds__(128) void ui_kernel(
    const float* __restrict__ u, const float* __restrict__ iv,
    const float* __restrict__ W0, const float* __restrict__ b0,
    const float* __restrict__ W1, const float* __restrict__ b1)
{
    __shared__ float sx[8][128];
    __shared__ float sh[8][128];
    int tid = threadIdx.x;
    int row0 = blockIdx.x * 8;
    #pragma unroll
    for (int rr = 0; rr < 8; rr++) {
        int row = row0 + rr;
        sx[rr][tid] = (tid < 64) ? u[row * 64 + tid] : iv[row * 64 + tid - 64];
    }
    __syncthreads();
    float acc[8];
    #pragma unroll
    for (int rr = 0; rr < 8; rr++) acc[rr] = 0.f;
    #pragma unroll 4
    for (int k = 0; k < 128; k++) {
        float w = W0[k * 128 + tid];
        #pragma unroll
        for (int rr = 0; rr < 8; rr++) acc[rr] += sx[rr][k] * w;
    }
    float bb = b0[tid];
    #pragma unroll
    for (int rr = 0; rr < 8; rr++) sh[rr][tid] = lrelu(acc[rr] + bb);
    __syncthreads();
    int j = tid & 63, rb = (tid >> 6) * 4;
    float a2[4] = {0.f, 0.f, 0.f, 0.f};
    #pragma unroll 4
    for (int k = 0; k < 128; k++) {
        float w = W1[k * 64 + j];
        #pragma unroll
        for (int q = 0; q < 4; q++) a2[q] += sh[rb + q][k] * w;
    }
    float b2 = b1[j];
    #pragma unroll
    for (int q = 0; q < 4; q++) g_ui[(row0 + rb + q) * 64 + j] = lrelu(a2[q] + b2);
}

// ---------------- zero + bin kernels ----------------
__global__ void zero_cnt_kernel() {
    if (threadIdx.x < RREL) g_cnt[threadIdx.x] = 0;
}

__global__ __launch_bounds__(512) void bin_kernel(const void* __restrict__ s_raw)
{
    __shared__ int bc[RREL], bb[RREL], sis64;
    int tid = threadIdx.x;
    if (tid == 0) {
        const int* p = (const int*)s_raw;
        int any = 0;
        for (int q = 1; q < 257; q += 2) any |= p[q];
        sis64 = (any == 0);
        bc[0] = bc[1] = bc[2] = 0;
    }
    __syncthreads();
    int it = blockIdx.x * 512 + tid;
    const int* s32 = (const int*)s_raw;
    int sv = sis64 ? s32[2 * it] : s32[it];
    sv = min(max(sv, 0), RREL - 1);
    int pos = atomicAdd(&bc[sv], 1);
    __syncthreads();
    if (tid < RREL) bb[tid] = atomicAdd(&g_cnt[tid], bc[tid]);
    __syncthreads();
    g_items[sv * BN + bb[sv] + pos] = it;
}

// ---------------- kernel C: bf16 mma.sync AO branch, 2 anti-phased warp-groups ----------------
#define XBYTES    17408
#define W0H_OFF   69632
#define W0L_OFF   104448
#define W1H_OFF   139264
#define W1L_OFF   156672
#define SB0_OFF   174080
#define SB1_OFF   174592
#define SL_OFF    174848
#define SRED_OFF  175360
#define SMEM_TOT  177408

#define ROWSTEP16 (16 * KP * 2)   // 4352 bytes

__global__ __launch_bounds__(512, 1) void ao_mma_kernel(
    const float* __restrict__ a_emb, const float* __restrict__ o_emb,
    const float* __restrict__ aoW0, const float* __restrict__ aob0,
    const float* __restrict__ aoW1, const float* __restrict__ aob1,
    float* __restrict__ out)
{
    extern __shared__ char smem[];
    unsigned sbase = smem_u32(smem);
    float* sb0 = (float*)(smem + SB0_OFF);
    float* sb1 = (float*)(smem + SB1_OFF);

    int tid = threadIdx.x, wid = tid >> 5, lane = tid & 31;
    int grp = wid >> 3;
    int wg  = wid & 7;
    int tg  = tid & 255;
    int gq = lane >> 2, t = lane & 3;
    int barid = 1 + grp;

    int*   slg   = (int*)(smem + SL_OFF) + grp * 64;
    float* sredg = (float*)(smem + SRED_OFF) + grp * 256;

    unsigned rowSel = (unsigned)(lane & 15);
    unsigned kSel   = (unsigned)((lane >> 4) << 3);

    int mrow  = (wg & 1) * 32;
    int ncol  = (wg >> 1) * 32;
    int ncol2 = (wg >> 1) * 16;

    unsigned xbase = sbase + (unsigned)grp * (2 * XBYTES);
    unsigned aHiB  = xbase + ((mrow + rowSel) * KP + kSel) * 2;
    unsigned aLoB  = aHiB + XBYTES;
    unsigned b0HiB = sbase + W0H_OFF + ((ncol + rowSel) * KP + kSel) * 2;
    unsigned b0LoB = b0HiB + (W0L_OFF - W0H_OFF);
    unsigned b1HiB = sbase + W1H_OFF + ((ncol2 + rowSel) * KP + kSel) * 2;
    unsigned b1LoB = b1HiB + (W1L_OFF - W1H_OFF);

    int cnt[RREL], rs[RREL + 1];
    rs[0] = 0;
    #pragma unroll
    for (int r = 0; r < RREL; r++) {
        cnt[r] = g_cnt[r];
        rs[r + 1] = rs[r] + ((cnt[r] + CH - 1) / CH);
    }
    int tot = rs[RREL];
    int per = (tot + gridDim.x - 1) / gridDim.x;
    int c_lo = blockIdx.x * per, c_hi = min(tot, c_lo + per);

    for (int r = 0; r < RREL; r++) {
        int lo = max(c_lo, rs[r]), hi = min(c_hi, rs[r + 1]);
        if (lo >= hi) continue;

        // ---- anti-phase staging: grp1 stages weights; grp0 pre-gathers chunk `lo` ----
        if (grp == 1) {
            const float* w0g = aoW0 + (size_t)r * 16384;
            for (int idx = tg; idx < 8192; idx += 256) {
                int n = idx & 127, k = (idx >> 7) * 2;
                unsigned hi_, lo_;
                split2(w0g[k * 128 + n], w0g[(k + 1) * 128 + n], hi_, lo_);
                *(unsigned*)(smem + W0H_OFF + (n * KP + k) * 2) = hi_;
                *(unsigned*)(smem + W0L_OFF + (n * KP + k) * 2) = lo_;
            }
            const float* w1g = aoW1 + (size_t)r * 8192;
            for (int idx = tg; idx < 4096; idx += 256) {
                int o = idx & 63, h = (idx >> 6) * 2;
                unsigned hi_, lo_;
                split2(w1g[h * 64 + o], w1g[(h + 1) * 64 + o], hi_, lo_);
                *(unsigned*)(smem + W1H_OFF + (o * KP + h) * 2) = hi_;
                *(unsigned*)(smem + W1L_OFF + (o * KP + h) * 2) = lo_;
            }
            if (tg < 128) sb0[tg] = aob0[r * 128 + tg];
            if (tg < 64)  sb1[tg] = aob1[r * 64 + tg];
        } else {
            // grp0 pre-gathers its first chunk (uses no weights)
            int ci = lo - rs[r];
            int base = ci * CH;
            int valid = min(CH, cnt[r] - base);
            if (tg < 64) slg[tg] = (tg < valid) ? g_items[r * BN + base + tg] : -1;
            BARG(1);
            int row = tg >> 2, q = tg & 3;
            int g = slg[row];
            int cb = q * 32;
            const float* src = (q < 2) ? a_emb + (size_t)max(g, 0) * 64 + cb
                                       : o_emb + (size_t)max(g, 0) * 64 + (cb - 64);
            #pragma unroll
            for (int i = 0; i < 8; i++) {
                float4 v = (g >= 0) ? *(const float4*)(src + i * 4)
                                    : make_float4(0.f, 0.f, 0.f, 0.f);
                unsigned h0, l0, h1, l1;
                split2(v.x, v.y, h0, l0);
                split2(v.z, v.w, h1, l1);
                int cc = cb + i * 4;
                unsigned d = xbase + (row * KP + cc) * 2 - sbase;
                *(unsigned*)(smem + d)              = h0;
                *(unsigned*)(smem + d + 4)          = h1;
                *(unsigned*)(smem + d + XBYTES)     = l0;
                *(unsigned*)(smem + d + XBYTES + 4) = l1;
            }
        }
        __syncthreads();

        // ---- group-interleaved chunk loop (grp0 leads by one gather phase) ----
        for (int c = lo + grp; c < hi; c += 2) {
            int ci = c - rs[r];
            int base = ci * CH;
            int valid = min(CH, cnt[r] - base);

            if (!(grp == 0 && c == lo)) {      // grp0's first chunk already gathered
                if (tg < 64) slg[tg] = (tg < valid) ? g_items[r * BN + base + tg] : -1;
                BARG(barid);
                int row = tg >> 2, q = tg & 3;
                int g = slg[row];
                int cb = q * 32;
                const float* src = (q < 2) ? a_emb + (size_t)max(g, 0) * 64 + cb
                                           : o_emb + (size_t)max(g, 0) * 64 + (cb - 64);
                #pragma unroll
                for (int i = 0; i < 8; i++) {
                    float4 v = (g >= 0) ? *(const float4*)(src + i * 4)
                                        : make_float4(0.f, 0.f, 0.f, 0.f);
                    unsigned h0, l0, h1, l1;
                    split2(v.x, v.y, h0, l0);
                    split2(v.z, v.w, h1, l1);
                    int cc = cb + i * 4;
                    unsigned d = xbase + (row * KP + cc) * 2 - sbase;
                    *(unsigned*)(smem + d)              = h0;
                    *(unsigned*)(smem + d + 4)          = h1;
                    *(unsigned*)(smem + d + XBYTES)     = l0;
                    *(unsigned*)(smem + d + XBYTES + 4) = l1;
                }
                BARG(barid);
            }

            // ---- GEMM1: D1[64,128] = X @ W0 (3-term split, term-major issue) ----
            float acc[2][4][4];
            #pragma unroll
            for (int i = 0; i < 2; i++)
                #pragma unroll
                for (int j = 0; j < 4; j++)
                    #pragma unroll
                    for (int q = 0; q < 4; q++) acc[i][j][q] = 0.f;

            #pragma unroll
            for (int kt = 0; kt < 8; kt++) {
                unsigned ko = (unsigned)kt * 32;
                unsigned ah[2][4], al[2][4], bh[4][2], bl[4][2];
                LDSM4(ah[0][0], ah[0][1], ah[0][2], ah[0][3], aHiB + ko);
                LDSM4(ah[1][0], ah[1][1], ah[1][2], ah[1][3], aHiB + ROWSTEP16 + ko);
                LDSM4(al[0][0], al[0][1], al[0][2], al[0][3], aLoB + ko);
                LDSM4(al[1][0], al[1][1], al[1][2], al[1][3], aLoB + ROWSTEP16 + ko);
                {
                    unsigned r0, r1, r2, r3;
                    LDSM4(r0, r1, r2, r3, b0HiB + ko);
                    bh[0][0] = r0; bh[1][0] = r1; bh[0][1] = r2; bh[1][1] = r3;
                    LDSM4(r0, r1, r2, r3, b0HiB + ROWSTEP16 + ko);
                    bh[2][0] = r0; bh[3][0] = r1; bh[2][1] = r2; bh[3][1] = r3;
                    LDSM4(r0, r1, r2, r3, b0LoB + ko);
                    bl[0][0] = r0; bl[1][0] = r1; bl[0][1] = r2; bl[1][1] = r3;
                    LDSM4(r0, r1, r2, r3, b0LoB + ROWSTEP16 + ko);
                    bl[2][0] = r0; bl[3][0] = r1; bl[2][1] = r2; bl[3][1] = r3;
                }
                #pragma unroll
                for (int na = 0; na < 4; na++) {
                    MMA(acc[0][na], ah[0], bh[na]);
                    MMA(acc[1][na], ah[1], bh[na]);
                }
                #pragma unroll
                for (int na = 0; na < 4; na++) {
                    MMA(acc[0][na], ah[0], bl[na]);
                    MMA(acc[1][na], ah[1], bl[na]);
                }
                #pragma unroll
                for (int na = 0; na < 4; na++) {
                    MMA(acc[0][na], al[0], bh[na]);
                    MMA(acc[1][na], al[1], bh[na]);
                }
            }
            BARG(barid);   // all X reads done before overwrite with H

            // ---- epilogue 1: H = lrelu(D1 + b0), split in place of X ----
            #pragma unroll
            for (int ma = 0; ma < 2; ma++) {
                int rr0 = mrow + ma * 16 + gq;
                #pragma unroll
                for (int na = 0; na < 4; na++) {
                    int cc = ncol + na * 8 + 2 * t;
                    float h0 = lrelu(acc[ma][na][0] + sb0[cc]);
                    float h1 = lrelu(acc[ma][na][1] + sb0[cc + 1]);
                    float h2 = lrelu(acc[ma][na][2] + sb0[cc]);
                    float h3 = lrelu(acc[ma][na][3] + sb0[cc + 1]);
                    unsigned hi_, lo_;
                    unsigned d = xbase + (rr0 * KP + cc) * 2 - sbase;
                    split2(h0, h1, hi_, lo_);
                    *(unsigned*)(smem + d)          = hi_;
                    *(unsigned*)(smem + d + XBYTES) = lo_;
                    split2(h2, h3, hi_, lo_);
                    unsigned d2 = d + 8 * KP * 2;
                    *(unsigned*)(smem + d2)          = hi_;
                    *(unsigned*)(smem + d2 + XBYTES) = lo_;
                }
            }
            BARG(barid);

            // ---- GEMM2: D2[64,64] = H @ W1 (term-major issue) ----
            float acc2[2][2][4];
            #pragma unroll
            for (int i = 0; i < 2; i++)
                #pragma unroll
                for (int j = 0; j < 2; j++)
                    #pragma unroll
                    for (int q = 0; q < 4; q++) acc2[i][j][q] = 0.f;

            #pragma unroll
            for (int kt = 0; kt < 8; kt++) {
                unsigned ko = (unsigned)kt * 32;
                unsigned ah[2][4], al[2][4], bh[2][2], bl[2][2];
                LDSM4(ah[0][0], ah[0][1], ah[0][2], ah[0][3], aHiB + ko);
                LDSM4(ah[1][0], ah[1][1], ah[1][2], ah[1][3], aHiB + ROWSTEP16 + ko);
                LDSM4(al[0][0], al[0][1], al[0][2], al[0][3], aLoB + ko);
                LDSM4(al[1][0], al[1][1], al[1][2], al[1][3], aLoB + ROWSTEP16 + ko);
                {
                    unsigned r0, r1, r2, r3;
                    LDSM4(r0, r1, r2, r3, b1HiB + ko);
                    bh[0][0] = r0; bh[1][0] = r1; bh[0][1] = r2; bh[1][1] = r3;
                    LDSM4(r0, r1, r2, r3, b1LoB + ko);
                    bl[0][0] = r0; bl[1][0] = r1; bl[0][1] = r2; bl[1][1] = r3;
                }
                #pragma unroll
                for (int na = 0; na < 2; na++) {
                    MMA(acc2[0][na], ah[0], bh[na]);
                    MMA(acc2[1][na], ah[1], bh[na]);
                }
                #pragma unroll
                for (int na = 0; na < 2; na++) {
                    MMA(acc2[0][na], ah[0], bl[na]);
                    MMA(acc2[1][na], ah[1], bl[na]);
                }
                #pragma unroll
                for (int na = 0; na < 2; na++) {
                    MMA(acc2[0][na], al[0], bh[na]);
                    MMA(acc2[1][na], al[1], bh[na]);
                }
            }

            // ---- epilogue 2: o = lrelu(D2 + b1); partial dot with ui; reduce ----
            #pragma unroll
            for (int ma = 0; ma < 2; ma++) {
                #pragma unroll
                for (int half = 0; half < 2; half++) {
                    int row = mrow + ma * 16 + gq + half * 8;
                    int g = slg[row];
                    const float* uiP = g_ui + (size_t)(max(g, 0) >> 5) * 64;
                    float p = 0.f;
                    #pragma unroll
                    for (int na = 0; na < 2; na++) {
                        int cc = ncol2 + na * 8 + 2 * t;
                        float2 uv = *(const float2*)(uiP + cc);
                        float o0 = lrelu(acc2[ma][na][half * 2]     + sb1[cc]);
                        float o1 = lrelu(acc2[ma][na][half * 2 + 1] + sb1[cc + 1]);
                        p += o0 * uv.x + o1 * uv.y;
                    }
                    p += __shfl_xor_sync(0xffffffffu, p, 1);
                    p += __shfl_xor_sync(0xffffffffu, p, 2);
                    if (t == 0) sredg[row * 4 + (wg >> 1)] = p;
                }
            }
            BARG(barid);
            if (tg < 64) {
                int g = slg[tg];
                if (g >= 0)
                    out[g] = sredg[tg * 4] + sredg[tg * 4 + 1]
                           + sredg[tg * 4 + 2] + sredg[tg * 4 + 3];
            }
            BARG(barid);
        }
        __syncthreads();
    }
}

// ---------------- launch ----------------
extern "C" void kernel_launch(void* const* d_in, const int* in_sizes, int n_in,
                              void* d_out, int out_size)
{
    const float* u    = (const float*)d_in[0];
    const float* iv   = (const float*)d_in[1];
    const float* a    = (const float*)d_in[2];
    const float* o    = (const float*)d_in[3];
    const void*  s    = d_in[4];
    const float* aoW0 = (const float*)d_in[5];
    const float* aob0 = (const float*)d_in[6];
    const float* aoW1 = (const float*)d_in[7];
    const float* aob1 = (const float*)d_in[8];
    const float* uiW0 = (const float*)d_in[9];
    const float* uib0 = (const float*)d_in[10];
    const float* uiW1 = (const float*)d_in[11];
    const float* uib1 = (const float*)d_in[12];
    float* out = (float*)d_out;

    cudaFuncSetAttribute(ao_mma_kernel, cudaFuncAttributeMaxDynamicSharedMemorySize, SMEM_TOT);
    int nsm = 148;
    cudaDeviceGetAttribute(&nsm, cudaDevAttrMultiProcessorCount, 0);

    zero_cnt_kernel<<<1, 32>>>();
    bin_kernel<<<BN / 512, 512>>>(s);
    ui_kernel<<<B_ / 8, 128>>>(u, iv, uiW0, uib0, uiW1, uib1);
    ao_mma_kernel<<<nsm, 512, SMEM_TOT>>>(a, o, aoW0, aob0, aoW1, aob1, out);
}

// round 14
// speedup vs baseline: 1.1497x; 1.0037x over previous
#include <cuda_runtime.h>
#include <cuda_bf16.h>

#define B_    8192
#define NPAIR 32
#define BN    (B_ * NPAIR)
#define RREL  3
#define KP    136            // padded bf16 row stride (conflict-free for ldmatrix)
#define CH    64             // items per chunk (per warp-group)

__device__ float g_ui[B_ * 64];
__device__ int   g_cnt[RREL];
__device__ int   g_items[RREL * BN];

__device__ __forceinline__ float lrelu(float x) { return x >= 0.f ? x : 0.01f * x; }

// Truncation-based 2-way bf16 split: hi = bit-truncated bf16 (exact residual),
// lo = rn(x - hi). Pair error <= 2^-17 |x|.
__device__ __forceinline__ void split2(float x0, float x1, unsigned& hi, unsigned& lo) {
    unsigned u0 = __float_as_uint(x0), u1 = __float_as_uint(x1);
    hi = __byte_perm(u0, u1, 0x7632);            // {u1[31:16], u0[31:16]}
    float l0 = x0 - __uint_as_float(u0 & 0xFFFF0000u);
    float l1 = x1 - __uint_as_float(u1 & 0xFFFF0000u);
    asm("cvt.rn.bf16x2.f32 %0, %1, %2;" : "=r"(lo) : "f"(l1), "f"(l0));
}

__device__ __forceinline__ unsigned smem_u32(const void* p) {
    unsigned a;
    asm("{ .reg .u64 t; cvta.to.shared.u64 t, %1; cvt.u32.u64 %0, t; }" : "=r"(a) : "l"(p));
    return a;
}

#define MMA(d, a, b) \
    asm volatile("mma.sync.aligned.m16n8k16.row.col.f32.bf16.bf16.f32 " \
        "{%0,%1,%2,%3}, {%4,%5,%6,%7}, {%8,%9}, {%0,%1,%2,%3};" \
        : "+f"((d)[0]), "+f"((d)[1]), "+f"((d)[2]), "+f"((d)[3]) \
        : "r"((a)[0]), "r"((a)[1]), "r"((a)[2]), "r"((a)[3]), "r"((b)[0]), "r"((b)[1]))

#define LDSM4(r0, r1, r2, r3, addr) \
    asm volatile("ldmatrix.sync.aligned.m8n8.x4.shared.b16 {%0,%1,%2,%3}, [%4];" \
        : "=r"(r0), "=r"(r1), "=r"(r2), "=r"(r3) : "r"(addr))

#define BARG(id) asm volatile("bar.sync %0, 256;" :: "r"(id) : "memory")

// ---------------- kernel A: ui branch (unchanged, passing) ----------------
__global__ __launch_bounds__(128) void ui_kernel(
    const float* __restrict__ u, const float* __restrict__ iv,
    const float* __restrict__ W0, const float* __restrict__ b0,
    const float* __restrict__ W1, const float* __restrict__ b1)
{
    __shared__ float sx[8][128];
    __shared__ float sh[8][128];
    int tid = threadIdx.x;
    int row0 = blockIdx.x * 8;
    #pragma unroll
    for (int rr = 0; rr < 8; rr++) {
        int row = row0 + rr;
        sx[rr][tid] = (tid < 64) ? u[row * 64 + tid] : iv[row * 64 + tid - 64];
    }
    __syncthreads();
    float acc[8];
    #pragma unroll
    for (int rr = 0; rr < 8; rr++) acc[rr] = 0.f;
    #pragma unroll 4
    for (int k = 0; k < 128; k++) {
        float w = W0[k * 128 + tid];
        #pragma unroll
        for (int rr = 0; rr < 8; rr++) acc[rr] += sx[rr][k] * w;
    }
    float bb = b0[tid];
    #pragma unroll
    for (int rr = 0; rr < 8; rr++) sh[rr][tid] = lrelu(acc[rr] + bb);
    __syncthreads();
    int j = tid & 63, rb = (tid >> 6) * 4;
    float a2[4] = {0.f, 0.f, 0.f, 0.f};
    #pragma unroll 4
    for (int k = 0; k < 128; k++) {
        float w = W1[k * 64 + j];
        #pragma unroll
        for (int q = 0; q < 4; q++) a2[q] += sh[rb + q][k] * w;
    }
    float b2 = b1[j];
    #pragma unroll
    for (int q = 0; q < 4; q++) g_ui[(row0 + rb + q) * 64 + j] = lrelu(a2[q] + b2);
}

// ---------------- zero + bin kernels ----------------
__global__ void zero_cnt_kernel() {
    if (threadIdx.x < RREL) g_cnt[threadIdx.x] = 0;
}

__global__ __launch_bounds__(512) void bin_kernel(const void* __restrict__ s_raw)
{
    __shared__ int bc[RREL], bb[RREL], sis64;
    int tid = threadIdx.x;
    if (tid == 0) {
        const int* p = (const int*)s_raw;
        int any = 0;
        for (int q = 1; q < 257; q += 2) any |= p[q];
        sis64 = (any == 0);
        bc[0] = bc[1] = bc[2] = 0;
    }
    __syncthreads();
    int it = blockIdx.x * 512 + tid;
    const int* s32 = (const int*)s_raw;
    int sv = sis64 ? s32[2 * it] : s32[it];
    sv = min(max(sv, 0), RREL - 1);
    int pos = atomicAdd(&bc[sv], 1);
    __syncthreads();
    if (tid < RREL) bb[tid] = atomicAdd(&g_cnt[tid], bc[tid]);
    __syncthreads();
    g_items[sv * BN + bb[sv] + pos] = it;
}

// ---------------- kernel C: bf16 mma.sync AO branch, 2 anti-phased warp-groups ----------------
#define XBYTES    17408
#define W0H_OFF   69632
#define W0L_OFF   104448
#define W1H_OFF   139264
#define W1L_OFF   156672
#define SB0_OFF   174080
#define SB1_OFF   174592
#define SL_OFF    174848
#define SRED_OFF  175360
#define SMEM_TOT  177408

#define ROWSTEP16 (16 * KP * 2)   // 4352 bytes

__global__ __launch_bounds__(512, 1) void ao_mma_kernel(
    const float* __restrict__ a_emb, const float* __restrict__ o_emb,
    const float* __restrict__ aoW0, const float* __restrict__ aob0,
    const float* __restrict__ aoW1, const float* __restrict__ aob1,
    float* __restrict__ out)
{
    extern __shared__ char smem[];
    unsigned sbase = smem_u32(smem);
    float* sb0 = (float*)(smem + SB0_OFF);
    float* sb1 = (float*)(smem + SB1_OFF);

    int tid = threadIdx.x, wid = tid >> 5, lane = tid & 31;
    int grp = wid >> 3;
    int wg  = wid & 7;
    int tg  = tid & 255;
    int gq = lane >> 2, t = lane & 3;
    int barid = 1 + grp;

    int*   slg   = (int*)(smem + SL_OFF) + grp * 64;
    float* sredg = (float*)(smem + SRED_OFF) + grp * 256;

    unsigned rowSel = (unsigned)(lane & 15);
    unsigned kSel   = (unsigned)((lane >> 4) << 3);

    int mrow  = (wg & 1) * 32;
    int ncol  = (wg >> 1) * 32;
    int ncol2 = (wg >> 1) * 16;

    unsigned xbase = sbase + (unsigned)grp * (2 * XBYTES);
    unsigned aHiB  = xbase + ((mrow + rowSel) * KP + kSel) * 2;
    unsigned aLoB  = aHiB + XBYTES;
    unsigned b0HiB = sbase + W0H_OFF + ((ncol + rowSel) * KP + kSel) * 2;
    unsigned b0LoB = b0HiB + (W0L_OFF - W0H_OFF);
    unsigned b1HiB = sbase + W1H_OFF + ((ncol2 + rowSel) * KP + kSel) * 2;
    unsigned b1LoB = b1HiB + (W1L_OFF - W1H_OFF);

    int cnt[RREL], rs[RREL + 1];
    rs[0] = 0;
    #pragma unroll
    for (int r = 0; r < RREL; r++) {
        cnt[r] = g_cnt[r];
        rs[r + 1] = rs[r] + ((cnt[r] + CH - 1) / CH);
    }
    int tot = rs[RREL];
    int per = (tot + gridDim.x - 1) / gridDim.x;
    int c_lo = blockIdx.x * per, c_hi = min(tot, c_lo + per);

    for (int r = 0; r < RREL; r++) {
        int lo = max(c_lo, rs[r]), hi = min(c_hi, rs[r + 1]);
        if (lo >= hi) continue;

        // ---- anti-phase staging: grp1 stages weights; grp0 pre-gathers chunk `lo` ----
        if (grp == 1) {
            const float* w0g = aoW0 + (size_t)r * 16384;
            for (int idx = tg; idx < 8192; idx += 256) {
                int n = idx & 127, k = (idx >> 7) * 2;
                unsigned hi_, lo_;
                split2(w0g[k * 128 + n], w0g[(k + 1) * 128 + n], hi_, lo_);
                *(unsigned*)(smem + W0H_OFF + (n * KP + k) * 2) = hi_;
                *(unsigned*)(smem + W0L_OFF + (n * KP + k) * 2) = lo_;
            }
            const float* w1g = aoW1 + (size_t)r * 8192;
            for (int idx = tg; idx < 4096; idx += 256) {
                int o = idx & 63, h = (idx >> 6) * 2;
                unsigned hi_, lo_;
                split2(w1g[h * 64 + o], w1g[(h + 1) * 64 + o], hi_, lo_);
                *(unsigned*)(smem + W1H_OFF + (o * KP + h) * 2) = hi_;
                *(unsigned*)(smem + W1L_OFF + (o * KP + h) * 2) = lo_;
            }
            if (tg < 128) sb0[tg] = aob0[r * 128 + tg];
            if (tg < 64)  sb1[tg] = aob1[r * 64 + tg];
        } else {
            // grp0 pre-gathers its first chunk (uses no weights)
            int ci = lo - rs[r];
            int base = ci * CH;
            int valid = min(CH, cnt[r] - base);
            if (tg < 64) slg[tg] = (tg < valid) ? g_items[r * BN + base + tg] : -1;
            BARG(1);
            int row = tg >> 2, q = tg & 3;
            int g = slg[row];
            int cb = q * 32;
            const float* src = (q < 2) ? a_emb + (size_t)max(g, 0) * 64 + cb
                                       : o_emb + (size_t)max(g, 0) * 64 + (cb - 64);
            #pragma unroll
            for (int i = 0; i < 8; i++) {
                float4 v = (g >= 0) ? *(const float4*)(src + i * 4)
                                    : make_float4(0.f, 0.f, 0.f, 0.f);
                unsigned h0, l0, h1, l1;
                split2(v.x, v.y, h0, l0);
                split2(v.z, v.w, h1, l1);
                int cc = cb + i * 4;
                unsigned d = xbase + (row * KP + cc) * 2 - sbase;
                *(unsigned*)(smem + d)              = h0;
                *(unsigned*)(smem + d + 4)          = h1;
                *(unsigned*)(smem + d + XBYTES)     = l0;
                *(unsigned*)(smem + d + XBYTES + 4) = l1;
            }
        }
        __syncthreads();

        // ---- group-interleaved chunk loop (grp0 leads by one gather phase) ----
        for (int c = lo + grp; c < hi; c += 2) {
            int ci = c - rs[r];
            int base = ci * CH;
            int valid = min(CH, cnt[r] - base);

            if (!(grp == 0 && c == lo)) {      // grp0's first chunk already gathered
                if (tg < 64) slg[tg] = (tg < valid) ? g_items[r * BN + base + tg] : -1;
                BARG(barid);
                int row = tg >> 2, q = tg & 3;
                int g = slg[row];
                int cb = q * 32;
                const float* src = (q < 2) ? a_emb + (size_t)max(g, 0) * 64 + cb
                                           : o_emb + (size_t)max(g, 0) * 64 + (cb - 64);
                #pragma unroll
                for (int i = 0; i < 8; i++) {
                    float4 v = (g >= 0) ? *(const float4*)(src + i * 4)
                                        : make_float4(0.f, 0.f, 0.f, 0.f);
                    unsigned h0, l0, h1, l1;
                    split2(v.x, v.y, h0, l0);
                    split2(v.z, v.w, h1, l1);
                    int cc = cb + i * 4;
                    unsigned d = xbase + (row * KP + cc) * 2 - sbase;
                    *(unsigned*)(smem + d)              = h0;
                    *(unsigned*)(smem + d + 4)          = h1;
                    *(unsigned*)(smem + d + XBYTES)     = l0;
                    *(unsigned*)(smem + d + XBYTES + 4) = l1;
                }
                BARG(barid);
            }

            // ---- GEMM1: D1[64,128] = X @ W0 (3-term split, term-major issue) ----
            float acc[2][4][4];
            #pragma unroll
            for (int i = 0; i < 2; i++)
                #pragma unroll
                for (int j = 0; j < 4; j++)
                    #pragma unroll
                    for (int q = 0; q < 4; q++) acc[i][j][q] = 0.f;

            #pragma unroll
            for (int kt = 0; kt < 8; kt++) {
                unsigned ko = (unsigned)kt * 32;
                unsigned ah[2][4], al[2][4], bh[4][2], bl[4][2];
                LDSM4(ah[0][0], ah[0][1], ah[0][2], ah[0][3], aHiB + ko);
                LDSM4(ah[1][0], ah[1][1], ah[1][2], ah[1][3], aHiB + ROWSTEP16 + ko);
                LDSM4(al[0][0], al[0][1], al[0][2], al[0][3], aLoB + ko);
                LDSM4(al[1][0], al[1][1], al[1][2], al[1][3], aLoB + ROWSTEP16 + ko);
                {
                    unsigned r0, r1, r2, r3;
                    LDSM4(r0, r1, r2, r3, b0HiB + ko);
                    bh[0][0] = r0; bh[1][0] = r1; bh[0][1] = r2; bh[1][1] = r3;
                    LDSM4(r0, r1, r2, r3, b0HiB + ROWSTEP16 + ko);
                    bh[2][0] = r0; bh[3][0] = r1; bh[2][1] = r2; bh[3][1] = r3;
                    LDSM4(r0, r1, r2, r3, b0LoB + ko);
                    bl[0][0] = r0; bl[1][0] = r1; bl[0][1] = r2; bl[1][1] = r3;
                    LDSM4(r0, r1, r2, r3, b0LoB + ROWSTEP16 + ko);
                    bl[2][0] = r0; bl[3][0] = r1; bl[2][1] = r2; bl[3][1] = r3;
                }
                #pragma unroll
                for (int na = 0; na < 4; na++) {
                    MMA(acc[0][na], ah[0], bh[na]);
                    MMA(acc[1][na], ah[1], bh[na]);
                }
                #pragma unroll
                for (int na = 0; na < 4; na++) {
                    MMA(acc[0][na], ah[0], bl[na]);
                    MMA(acc[1][na], ah[1], bl[na]);
                }
                #pragma unroll
                for (int na = 0; na < 4; na++) {
                    MMA(acc[0][na], al[0], bh[na]);
                    MMA(acc[1][na], al[1], bh[na]);
                }
            }
            BARG(barid);   // all X reads done before overwrite with H

            // ---- epilogue 1: H = lrelu(D1 + b0), split in place of X ----
            #pragma unroll
            for (int ma = 0; ma < 2; ma++) {
                int rr0 = mrow + ma * 16 + gq;
                #pragma unroll
                for (int na = 0; na < 4; na++) {
                    int cc = ncol + na * 8 + 2 * t;
                    float h0 = lrelu(acc[ma][na][0] + sb0[cc]);
                    float h1 = lrelu(acc[ma][na][1] + sb0[cc + 1]);
                    float h2 = lrelu(acc[ma][na][2] + sb0[cc]);
                    float h3 = lrelu(acc[ma][na][3] + sb0[cc + 1]);
                    unsigned hi_, lo_;
                    unsigned d = xbase + (rr0 * KP + cc) * 2 - sbase;
                    split2(h0, h1, hi_, lo_);
                    *(unsigned*)(smem + d)          = hi_;
                    *(unsigned*)(smem + d + XBYTES) = lo_;
                    split2(h2, h3, hi_, lo_);
                    unsigned d2 = d + 8 * KP * 2;
                    *(unsigned*)(smem + d2)          = hi_;
                    *(unsigned*)(smem + d2 + XBYTES) = lo_;
                }
            }
            BARG(barid);

            // ---- GEMM2: D2[64,64] = H @ W1 (term-major issue) ----
            float acc2[2][2][4];
            #pragma unroll
            for (int i = 0; i < 2; i++)
                #pragma unroll
                for (int j = 0; j < 2; j++)
                    #pragma unroll
                    for (int q = 0; q < 4; q++) acc2[i][j][q] = 0.f;

            #pragma unroll
            for (int kt = 0; kt < 8; kt++) {
                unsigned ko = (unsigned)kt * 32;
                unsigned ah[2][4], al[2][4], bh[2][2], bl[2][2];
                LDSM4(ah[0][0], ah[0][1], ah[0][2], ah[0][3], aHiB + ko);
                LDSM4(ah[1][0], ah[1][1], ah[1][2], ah[1][3], aHiB + ROWSTEP16 + ko);
                LDSM4(al[0][0], al[0][1], al[0][2], al[0][3], aLoB + ko);
                LDSM4(al[1][0], al[1][1], al[1][2], al[1][3], aLoB + ROWSTEP16 + ko);
                {
                    unsigned r0, r1, r2, r3;
                    LDSM4(r0, r1, r2, r3, b1HiB + ko);
                    bh[0][0] = r0; bh[1][0] = r1; bh[0][1] = r2; bh[1][1] = r3;
                    LDSM4(r0, r1, r2, r3, b1LoB + ko);
                    bl[0][0] = r0; bl[1][0] = r1; bl[0][1] = r2; bl[1][1] = r3;
                }
                #pragma unroll
                for (int na = 0; na < 2; na++) {
                    MMA(acc2[0][na], ah[0], bh[na]);
                    MMA(acc2[1][na], ah[1], bh[na]);
                }
                #pragma unroll
                for (int na = 0; na < 2; na++) {
                    MMA(acc2[0][na], ah[0], bl[na]);
                    MMA(acc2[1][na], ah[1], bl[na]);
                }
                #pragma unroll
                for (int na = 0; na < 2; na++) {
                    MMA(acc2[0][na], al[0], bh[na]);
                    MMA(acc2[1][na], al[1], bh[na]);
                }
            }

            // ---- epilogue 2: o = lrelu(D2 + b1); partial dot with ui; reduce ----
            #pragma unroll
            for (int ma = 0; ma < 2; ma++) {
                #pragma unroll
                for (int half = 0; half < 2; half++) {
                    int row = mrow + ma * 16 + gq + half * 8;
                    int g = slg[row];
                    const float* uiP = g_ui + (size_t)(max(g, 0) >> 5) * 64;
                    float p = 0.f;
                    #pragma unroll
                    for (int na = 0; na < 2; na++) {
                        int cc = ncol2 + na * 8 + 2 * t;
                        float2 uv = *(const float2*)(uiP + cc);
                        float o0 = lrelu(acc2[ma][na][half * 2]     + sb1[cc]);
                        float o1 = lrelu(acc2[ma][na][half * 2 + 1] + sb1[cc + 1]);
                        p += o0 * uv.x + o1 * uv.y;
                    }
                    p += __shfl_xor_sync(0xffffffffu, p, 1);
                    p += __shfl_xor_sync(0xffffffffu, p, 2);
                    if (t == 0) sredg[row * 4 + (wg >> 1)] = p;
                }
            }
            BARG(barid);
            if (tg < 64) {
                int g = slg[tg];
                if (g >= 0)
                    out[g] = sredg[tg * 4] + sredg[tg * 4 + 1]
                           + sredg[tg * 4 + 2] + sredg[tg * 4 + 3];
            }
            BARG(barid);
        }
        __syncthreads();
    }
}

// ---------------- launch ----------------
extern "C" void kernel_launch(void* const* d_in, const int* in_sizes, int n_in,
                              void* d_out, int out_size)
{
    const float* u    = (const float*)d_in[0];
    const float* iv   = (const float*)d_in[1];
    const float* a    = (const float*)d_in[2];
    const float* o    = (const float*)d_in[3];
    const void*  s    = d_in[4];
    const float* aoW0 = (const float*)d_in[5];
    const float* aob0 = (const float*)d_in[6];
    const float* aoW1 = (const float*)d_in[7];
    const float* aob1 = (const float*)d_in[8];
    const float* uiW0 = (const float*)d_in[9];
    const float* uib0 = (const float*)d_in[10];
    const float* uiW1 = (const float*)d_in[11];
    const float* uib1 = (const float*)d_in[12];
    float* out = (float*)d_out;

    cudaFuncSetAttribute(ao_mma_kernel, cudaFuncAttributeMaxDynamicSharedMemorySize, SMEM_TOT);
    int nsm = 148;
    cudaDeviceGetAttribute(&nsm, cudaDevAttrMultiProcessorCount, 0);

    zero_cnt_kernel<<<1, 32>>>();
    bin_kernel<<<BN / 512, 512>>>(s);
    ui_kernel<<<B_ / 8, 128>>>(u, iv, uiW0, uib0, uiW1, uib1);
    ao_mma_kernel<<<nsm, 512, SMEM_TOT>>>(a, o, aoW0, aob0, aoW1, aob1, out);
}